// round 2
// baseline (speedup 1.0000x reference)
#include <cuda_runtime.h>
#include <math.h>

#define HIDDEN 4096
#define NHEADS 32
#define DK     128
#define BATCH  2
#define SEQ    2048
#define MTOK   (BATCH*SEQ)

// attention tiling
#define AQ    128
#define AK    128
#define SS_LD 132   // padded leading dim: multiple of 4 (float4-aligned), mod 32 = 4 (no bank conflicts)

// Scratch (allocation-free rule: __device__ globals)
__device__ float g_q [MTOK * HIDDEN];
__device__ float g_k [MTOK * HIDDEN];
__device__ float g_v [MTOK * HIDDEN];
__device__ float g_ao[MTOK * HIDDEN];

// ----------------------------------------------------------------------------
// C[M,N] = A[M,K] @ B[N,K]^T   (fp32, 128x128x8 tiles, 8x8 per thread)
// ----------------------------------------------------------------------------
__global__ __launch_bounds__(256) void gemm_nt(const float* __restrict__ A,
                                               const float* __restrict__ B,
                                               float* __restrict__ C,
                                               int M, int N, int K)
{
    __shared__ float As[8][128];
    __shared__ float Bs[8][128];

    const int bm  = blockIdx.y * 128;
    const int bn  = blockIdx.x * 128;
    const int tid = threadIdx.x;
    const int tmb = (tid / 16) * 8;
    const int tnb = (tid % 16) * 8;

    // global->smem loaders: one float4 of A and B per thread per k-step
    const int lr = tid >> 1;          // 0..127
    const int lc = (tid & 1) * 4;     // 0 or 4
    const float* Ap = A + (size_t)(bm + lr) * K + lc;
    const float* Bp = B + (size_t)(bn + lr) * K + lc;

    float acc[8][8] = {};

    for (int k0 = 0; k0 < K; k0 += 8) {
        float4 av = *(const float4*)(Ap + k0);
        float4 bv = *(const float4*)(Bp + k0);
        As[lc + 0][lr] = av.x; As[lc + 1][lr] = av.y;
        As[lc + 2][lr] = av.z; As[lc + 3][lr] = av.w;
        Bs[lc + 0][lr] = bv.x; Bs[lc + 1][lr] = bv.y;
        Bs[lc + 2][lr] = bv.z; Bs[lc + 3][lr] = bv.w;
        __syncthreads();

        #pragma unroll
        for (int kk = 0; kk < 8; kk++) {
            float rm[8], rn[8];
            *(float4*)&rm[0] = *(const float4*)&As[kk][tmb];
            *(float4*)&rm[4] = *(const float4*)&As[kk][tmb + 4];
            *(float4*)&rn[0] = *(const float4*)&Bs[kk][tnb];
            *(float4*)&rn[4] = *(const float4*)&Bs[kk][tnb + 4];
            #pragma unroll
            for (int i = 0; i < 8; i++)
                #pragma unroll
                for (int j = 0; j < 8; j++)
                    acc[i][j] += rm[i] * rn[j];
        }
        __syncthreads();
    }

    #pragma unroll
    for (int i = 0; i < 8; i++) {
        float* cp = C + (size_t)(bm + tmb + i) * N + bn + tnb;
        *(float4*)(cp + 0) = make_float4(acc[i][0], acc[i][1], acc[i][2], acc[i][3]);
        *(float4*)(cp + 4) = make_float4(acc[i][4], acc[i][5], acc[i][6], acc[i][7]);
    }
}

// ----------------------------------------------------------------------------
// Flash attention, fp32. One CTA per (b, h, 128-row q tile).
// Q,K,V token-major [B,S,H*DK]. Output to g_ao same layout.
// ----------------------------------------------------------------------------
__global__ __launch_bounds__(256) void attn_kernel(const float* __restrict__ Qg,
                                                   const float* __restrict__ Kg,
                                                   const float* __restrict__ Vg,
                                                   float* __restrict__ Og)
{
    extern __shared__ float sm[];
    float* sQ   = sm;                      // [DK][AQ]  (d-major, Q transposed)
    float* sKV  = sQ  + DK * AQ;           // K phase: [DK][AK]; V phase: [AK][DK]
    float* sS   = sKV + DK * AK;           // scores, TRANSPOSED: [AK][SS_LD]  sS[j][i]
    float* rmax = sS  + AK * SS_LD;        // [AQ]
    float* rsum = rmax + AQ;               // [AQ]
    float* rcor = rsum + AQ;               // [AQ]

    const int tid = threadIdx.x;
    const int q0  = blockIdx.x * AQ;
    const int h   = blockIdx.y;
    const int b   = blockIdx.z;
    const size_t base = ((size_t)b * SEQ) * HIDDEN + (size_t)h * DK;
    const float scale = 0.08838834764831845f;   // 1/sqrt(128)

    // load Q tile, scaled, transposed to sQ[d][i]
    #pragma unroll
    for (int it = 0; it < (AQ * DK) / (256 * 4); it++) {
        int li = (it * 256 + tid) * 4;
        int i = li / DK, d = li % DK;
        float4 v = *(const float4*)(Qg + base + (size_t)(q0 + i) * HIDDEN + d);
        sQ[(d + 0) * AQ + i] = v.x * scale;
        sQ[(d + 1) * AQ + i] = v.y * scale;
        sQ[(d + 2) * AQ + i] = v.z * scale;
        sQ[(d + 3) * AQ + i] = v.w * scale;
    }
    if (tid < AQ) { rmax[tid] = -INFINITY; rsum[tid] = 0.0f; }

    const int tmb = (tid / 16) * 8;   // query rows (and output rows)
    const int tnb = (tid % 16) * 8;   // key cols / output dims
    float oacc[8][8] = {};

    for (int k0 = 0; k0 < SEQ; k0 += AK) {
        __syncthreads();  // previous PV done with sKV/sS

        // load K tile transposed: sKV[d][j]
        #pragma unroll
        for (int it = 0; it < (AK * DK) / (256 * 4); it++) {
            int li = (it * 256 + tid) * 4;
            int j = li / DK, d = li % DK;
            float4 v = *(const float4*)(Kg + base + (size_t)(k0 + j) * HIDDEN + d);
            sKV[(d + 0) * AK + j] = v.x;
            sKV[(d + 1) * AK + j] = v.y;
            sKV[(d + 2) * AK + j] = v.z;
            sKV[(d + 3) * AK + j] = v.w;
        }
        __syncthreads();

        // S = (Q*scale) K^T, 8x8 per thread
        float sacc[8][8] = {};
        #pragma unroll 8
        for (int d = 0; d < DK; d++) {
            float rm[8], rn[8];
            *(float4*)&rm[0] = *(const float4*)&sQ [d * AQ + tmb];
            *(float4*)&rm[4] = *(const float4*)&sQ [d * AQ + tmb + 4];
            *(float4*)&rn[0] = *(const float4*)&sKV[d * AK + tnb];
            *(float4*)&rn[4] = *(const float4*)&sKV[d * AK + tnb + 4];
            #pragma unroll
            for (int i = 0; i < 8; i++)
                #pragma unroll
                for (int j = 0; j < 8; j++)
                    sacc[i][j] += rm[i] * rn[j];
        }
        // write transposed: sS[j][i]
        #pragma unroll
        for (int j = 0; j < 8; j++) {
            float* sp = sS + (size_t)(tnb + j) * SS_LD + tmb;
            *(float4*)(sp + 0) = make_float4(sacc[0][j], sacc[1][j], sacc[2][j], sacc[3][j]);
            *(float4*)(sp + 4) = make_float4(sacc[4][j], sacc[5][j], sacc[6][j], sacc[7][j]);
        }
        __syncthreads();  // sS ready, sKV free

        // load V tile row-major: sKV[j][d]   (all threads)
        #pragma unroll
        for (int it = 0; it < (AK * DK) / (256 * 4); it++) {
            int li = (it * 256 + tid) * 4;
            int j = li / DK, d = li % DK;
            *(float4*)(sKV + (size_t)j * DK + d) =
                *(const float4*)(Vg + base + (size_t)(k0 + j) * HIDDEN + d);
        }
        // streaming softmax, one thread per query row (threads 0..127)
        if (tid < AQ) {
            const int r = tid;
            float m0 = rmax[r];
            float tmax = m0;
            #pragma unroll 8
            for (int j = 0; j < AK; j++)
                tmax = fmaxf(tmax, sS[(size_t)j * SS_LD + r]);
            float corr = __expf(m0 - tmax);
            float s = 0.0f;
            #pragma unroll 8
            for (int j = 0; j < AK; j++) {
                float e = __expf(sS[(size_t)j * SS_LD + r] - tmax);
                sS[(size_t)j * SS_LD + r] = e;
                s += e;
            }
            rmax[r] = tmax;
            rsum[r] = rsum[r] * corr + s;
            rcor[r] = corr;
        }
        __syncthreads();

        // rescale accumulators, then O += P @ V
        #pragma unroll
        for (int i = 0; i < 8; i++) {
            float c = rcor[tmb + i];
            #pragma unroll
            for (int j = 0; j < 8; j++) oacc[i][j] *= c;
        }
        #pragma unroll 4
        for (int j = 0; j < AK; j++) {
            float rp[8], rv[8];
            *(float4*)&rp[0] = *(const float4*)&sS [(size_t)j * SS_LD + tmb];
            *(float4*)&rp[4] = *(const float4*)&sS [(size_t)j * SS_LD + tmb + 4];
            *(float4*)&rv[0] = *(const float4*)&sKV[(size_t)j * DK + tnb];
            *(float4*)&rv[4] = *(const float4*)&sKV[(size_t)j * DK + tnb + 4];
            #pragma unroll
            for (int i = 0; i < 8; i++)
                #pragma unroll
                for (int jj = 0; jj < 8; jj++)
                    oacc[i][jj] += rp[i] * rv[jj];
        }
    }

    // finalize: divide by row sums, write token-major [B,S,H*DK]
    #pragma unroll
    for (int i = 0; i < 8; i++) {
        float inv = 1.0f / rsum[tmb + i];
        float* op = Og + base + (size_t)(q0 + tmb + i) * HIDDEN + tnb;
        *(float4*)(op + 0) = make_float4(oacc[i][0] * inv, oacc[i][1] * inv,
                                         oacc[i][2] * inv, oacc[i][3] * inv);
        *(float4*)(op + 4) = make_float4(oacc[i][4] * inv, oacc[i][5] * inv,
                                         oacc[i][6] * inv, oacc[i][7] * inv);
    }
}

// ----------------------------------------------------------------------------
extern "C" void kernel_launch(void* const* d_in, const int* in_sizes, int n_in,
                              void* d_out, int out_size)
{
    const float* x  = (const float*)d_in[0];
    const float* wq = (const float*)d_in[1];
    const float* wk = (const float*)d_in[2];
    const float* wv = (const float*)d_in[3];
    const float* wo = (const float*)d_in[4];
    float* out = (float*)d_out;

    float *qp, *kp, *vp, *aop;
    cudaGetSymbolAddress((void**)&qp,  g_q);
    cudaGetSymbolAddress((void**)&kp,  g_k);
    cudaGetSymbolAddress((void**)&vp,  g_v);
    cudaGetSymbolAddress((void**)&aop, g_ao);

    dim3 gg(HIDDEN / 128, MTOK / 128);   // (32, 32)
    gemm_nt<<<gg, 256>>>(x, wq, qp, MTOK, HIDDEN, HIDDEN);
    gemm_nt<<<gg, 256>>>(x, wk, kp, MTOK, HIDDEN, HIDDEN);
    gemm_nt<<<gg, 256>>>(x, wv, vp, MTOK, HIDDEN, HIDDEN);

    size_t smem = (size_t)(DK * AQ + DK * AK + AK * SS_LD + 3 * AQ) * sizeof(float);
    cudaFuncSetAttribute(attn_kernel, cudaFuncAttributeMaxDynamicSharedMemorySize,
                         (int)smem);
    dim3 ga(SEQ / AQ, NHEADS, BATCH);    // (16, 32, 2)
    attn_kernel<<<ga, 256, smem>>>(qp, kp, vp, aop);

    gemm_nt<<<gg, 256>>>(aop, wo, out, MTOK, HIDDEN, HIDDEN);
}

// round 4
// speedup vs baseline: 2.3145x; 2.3145x over previous
#include <cuda_runtime.h>
#include <cuda_bf16.h>
#include <math.h>
#include <stdint.h>

#define HIDDEN 4096
#define NHEADS 32
#define DK     128
#define BATCH  2
#define SEQ    2048
#define MTOK   (BATCH*SEQ)   // 4096

// GEMM tiling (mma.sync bf16)
#define MT 128
#define NT 128
#define KC 64                  // bf16 per chunk = 128 bytes/row (SW128)
#define NCHUNK (HIDDEN / KC)   // 64
#define TILE_BYTES (128 * 128) // 128 rows x 128B = 16KB
#define STAGE_BYTES (4 * TILE_BYTES)
#define SMEM_GEMM (2 * STAGE_BYTES)   // 128KB

// attention tiling (fp32 path, unchanged)
#define AQ 128
#define AK 128
#define SS_LD 132

// ---------------- scratch ----------------------------------------------------
__device__ float g_q [MTOK * HIDDEN];
__device__ float g_k [MTOK * HIDDEN];
__device__ float g_v [MTOK * HIDDEN];
__device__ float g_ao[MTOK * HIDDEN];

__device__ __nv_bfloat16 g_xh [MTOK * HIDDEN];
__device__ __nv_bfloat16 g_xl [MTOK * HIDDEN];
__device__ __nv_bfloat16 g_wqh[HIDDEN * HIDDEN];
__device__ __nv_bfloat16 g_wql[HIDDEN * HIDDEN];
__device__ __nv_bfloat16 g_wkh[HIDDEN * HIDDEN];
__device__ __nv_bfloat16 g_wkl[HIDDEN * HIDDEN];
__device__ __nv_bfloat16 g_wvh[HIDDEN * HIDDEN];
__device__ __nv_bfloat16 g_wvl[HIDDEN * HIDDEN];
__device__ __nv_bfloat16 g_woh[HIDDEN * HIDDEN];
__device__ __nv_bfloat16 g_wol[HIDDEN * HIDDEN];
__device__ __nv_bfloat16 g_aoh[MTOK * HIDDEN];
__device__ __nv_bfloat16 g_aol[MTOK * HIDDEN];

// ---------------- PTX helpers (portable ISA only: sm_80-level) ---------------
__device__ __forceinline__ uint32_t smem_u32(const void* p) {
    uint32_t a;
    asm("{ .reg .u64 t; cvta.to.shared.u64 t, %1; cvt.u32.u64 %0, t; }"
        : "=r"(a) : "l"(p));
    return a;
}
__device__ __forceinline__ void cp16(uint32_t dst, const void* src) {
    asm volatile("cp.async.cg.shared.global [%0], [%1], 16;"
                 :: "r"(dst), "l"(src) : "memory");
}
#define CP_COMMIT() asm volatile("cp.async.commit_group;" ::: "memory")
#define CP_WAIT(n)  asm volatile("cp.async.wait_group %0;" :: "n"(n) : "memory")

__device__ __forceinline__ void ldsm_x4(uint32_t& r0, uint32_t& r1,
                                        uint32_t& r2, uint32_t& r3, uint32_t a) {
    asm volatile("ldmatrix.sync.aligned.m8n8.x4.shared.b16 {%0,%1,%2,%3}, [%4];"
                 : "=r"(r0), "=r"(r1), "=r"(r2), "=r"(r3) : "r"(a));
}
__device__ __forceinline__ void mma_bf16(float* c, const uint32_t* a,
                                         uint32_t b0, uint32_t b1) {
    asm volatile(
        "mma.sync.aligned.m16n8k16.row.col.f32.bf16.bf16.f32 "
        "{%0,%1,%2,%3}, {%4,%5,%6,%7}, {%8,%9}, {%0,%1,%2,%3};"
        : "+f"(c[0]), "+f"(c[1]), "+f"(c[2]), "+f"(c[3])
        : "r"(a[0]), "r"(a[1]), "r"(a[2]), "r"(a[3]), "r"(b0), "r"(b1));
}

// ---------------- fp32 -> bf16 hi/lo split ------------------------------------
__global__ __launch_bounds__(256) void cvt_hilo(const float4* __restrict__ s,
                                                __nv_bfloat162* __restrict__ h,
                                                __nv_bfloat162* __restrict__ l)
{
    size_t i = (size_t)blockIdx.x * 256 + threadIdx.x;
    float4 v = s[i];
    __nv_bfloat16 hx = __float2bfloat16(v.x);
    __nv_bfloat16 hy = __float2bfloat16(v.y);
    __nv_bfloat16 hz = __float2bfloat16(v.z);
    __nv_bfloat16 hw = __float2bfloat16(v.w);
    __nv_bfloat16 lx = __float2bfloat16(v.x - __bfloat162float(hx));
    __nv_bfloat16 ly = __float2bfloat16(v.y - __bfloat162float(hy));
    __nv_bfloat16 lz = __float2bfloat16(v.z - __bfloat162float(hz));
    __nv_bfloat16 lw = __float2bfloat16(v.w - __bfloat162float(hw));
    h[2*i]   = __halves2bfloat162(hx, hy);
    h[2*i+1] = __halves2bfloat162(hz, hw);
    l[2*i]   = __halves2bfloat162(lx, ly);
    l[2*i+1] = __halves2bfloat162(lz, lw);
}

// ---------------- bf16 3-pass GEMM via mma.sync -------------------------------
// C[M,N] = (Ah+Al)[M,K] @ (Bh+Bl)[N,K]^T, dropping Al*Bl.
// smem stage: 4 tiles (Ah, Al, Bh, Bl), each 128 rows x 64 bf16, SW128 swizzle.
__global__ __launch_bounds__(256)
void gemm_mma_3p(const __nv_bfloat16* __restrict__ Ah,
                 const __nv_bfloat16* __restrict__ Al,
                 const __nv_bfloat16* __restrict__ Bh,
                 const __nv_bfloat16* __restrict__ Bl,
                 float* __restrict__ C)
{
    extern __shared__ __align__(1024) char smem[];
    const uint32_t sb = smem_u32(smem);
    const int tid  = threadIdx.x;
    const int wid  = tid >> 5;
    const int lane = tid & 31;
    const int bm   = blockIdx.y * MT;
    const int bn   = blockIdx.x * NT;

    // warp tile: 64x32 at (wm0, wn0); warp grid 2 (m) x 4 (n)
    const int wm0 = (wid & 1) * 64;
    const int wn0 = (wid >> 1) * 32;

    // global sources (byte pointers), per tile
    const char* gsrc[4] = {
        (const char*)Ah + (size_t)bm * (HIDDEN * 2),
        (const char*)Al + (size_t)bm * (HIDDEN * 2),
        (const char*)Bh + (size_t)bn * (HIDDEN * 2),
        (const char*)Bl + (size_t)bn * (HIDDEN * 2)
    };

    // loader precompute: this thread's 4 units per tile
    // unit idx = r*256 + tid -> row = idx>>3, u = idx&7
    uint32_t ld_sw [4];   // swizzled smem offset within tile
    uint32_t ld_go [4];   // global byte offset within row block (row*8192 + u*16)
    #pragma unroll
    for (int r = 0; r < 4; r++) {
        int idx = r * 256 + tid;
        uint32_t bo = (uint32_t)idx << 4;
        ld_sw[r] = bo ^ ((bo >> 3) & 0x70);
        ld_go[r] = (uint32_t)(idx >> 3) * (HIDDEN * 2) + (uint32_t)(idx & 7) * 16;
    }

    // ldmatrix address precompute (offsets within a tile, before stage/tile base)
    // A: threads 0-15 rows m0+t (k0), 16-31 rows m0+t-16 (k0+8)
    const int a_r   = lane & 15;
    const uint32_t a_k16 = (lane >> 4) * 16;          // byte offset for k+8
    uint32_t a_rb[4], a_xm[4];
    #pragma unroll
    for (int i = 0; i < 4; i++) {
        int row = wm0 + i * 16 + a_r;
        a_rb[i] = (uint32_t)row * 128;
        a_xm[i] = (uint32_t)(row & 7) * 16;
    }
    // B: group g = lane>>3: row = n0 + ((g&2)?8:0) + (lane&7); kbyte += (g&1)*16
    const int b_r   = ((lane >> 4) & 1) * 8 + (lane & 7);
    const uint32_t b_k16 = ((lane >> 3) & 1) * 16;
    uint32_t b_rb[2], b_xm[2];
    #pragma unroll
    for (int j = 0; j < 2; j++) {
        int row = wn0 + j * 16 + b_r;
        b_rb[j] = (uint32_t)row * 128;
        b_xm[j] = (uint32_t)(row & 7) * 16;
    }

    float acc[4][4][4] = {};

    // ---- pipeline ----
    auto load_stage = [&](int s, int c) {
        const uint32_t st = sb + (uint32_t)s * STAGE_BYTES;
        #pragma unroll
        for (int t = 0; t < 4; t++) {
            const char* g = gsrc[t] + (size_t)c * 128;
            const uint32_t tb = st + (uint32_t)t * TILE_BYTES;
            #pragma unroll
            for (int r = 0; r < 4; r++)
                cp16(tb + ld_sw[r], g + ld_go[r]);
        }
        CP_COMMIT();
    };

    load_stage(0, 0);

    for (int c = 0; c < NCHUNK; c++) {
        if (c + 1 < NCHUNK) {
            load_stage((c + 1) & 1, c + 1);
            CP_WAIT(1);
        } else {
            CP_WAIT(0);
        }
        __syncthreads();

        const uint32_t st  = sb + (uint32_t)(c & 1) * STAGE_BYTES;
        const uint32_t tAh = st;
        const uint32_t tAl = st + TILE_BYTES;
        const uint32_t tBh = st + 2 * TILE_BYTES;
        const uint32_t tBl = st + 3 * TILE_BYTES;

        #pragma unroll
        for (int ks = 0; ks < 4; ks++) {
            const uint32_t ak = (uint32_t)ks * 32 + a_k16;
            const uint32_t bk = (uint32_t)ks * 32 + b_k16;

            uint32_t ah[4][4], al[4][4], bh[2][4], bl[2][4];
            #pragma unroll
            for (int i = 0; i < 4; i++) {
                uint32_t off = a_rb[i] + (ak ^ a_xm[i]);
                ldsm_x4(ah[i][0], ah[i][1], ah[i][2], ah[i][3], tAh + off);
                ldsm_x4(al[i][0], al[i][1], al[i][2], al[i][3], tAl + off);
            }
            #pragma unroll
            for (int j = 0; j < 2; j++) {
                uint32_t off = b_rb[j] + (bk ^ b_xm[j]);
                ldsm_x4(bh[j][0], bh[j][1], bh[j][2], bh[j][3], tBh + off);
                ldsm_x4(bl[j][0], bl[j][1], bl[j][2], bl[j][3], tBl + off);
            }
            #pragma unroll
            for (int i = 0; i < 4; i++) {
                #pragma unroll
                for (int j = 0; j < 4; j++) {
                    uint32_t B0h = bh[j >> 1][(j & 1) * 2];
                    uint32_t B1h = bh[j >> 1][(j & 1) * 2 + 1];
                    uint32_t B0l = bl[j >> 1][(j & 1) * 2];
                    uint32_t B1l = bl[j >> 1][(j & 1) * 2 + 1];
                    mma_bf16(acc[i][j], ah[i], B0h, B1h);
                    mma_bf16(acc[i][j], ah[i], B0l, B1l);
                    mma_bf16(acc[i][j], al[i], B0h, B1h);
                }
            }
        }
        __syncthreads();
    }

    // ---- epilogue: write C ----
    const int cr = lane >> 2;           // 0..7
    const int cc = (lane & 3) * 2;      // 0,2,4,6
    #pragma unroll
    for (int i = 0; i < 4; i++) {
        #pragma unroll
        for (int j = 0; j < 4; j++) {
            int row = bm + wm0 + i * 16 + cr;
            int col = bn + wn0 + j * 8 + cc;
            float* p0 = C + (size_t)row * HIDDEN + col;
            float* p1 = C + (size_t)(row + 8) * HIDDEN + col;
            *(float2*)p0 = make_float2(acc[i][j][0], acc[i][j][1]);
            *(float2*)p1 = make_float2(acc[i][j][2], acc[i][j][3]);
        }
    }
}

// ---------------- flash attention, fp32 (unchanged, proven) -------------------
__global__ __launch_bounds__(256) void attn_kernel(const float* __restrict__ Qg,
                                                   const float* __restrict__ Kg,
                                                   const float* __restrict__ Vg,
                                                   float* __restrict__ Og)
{
    extern __shared__ float sm[];
    float* sQ   = sm;
    float* sKV  = sQ  + DK * AQ;
    float* sS   = sKV + DK * AK;
    float* rmax = sS  + AK * SS_LD;
    float* rsum = rmax + AQ;
    float* rcor = rsum + AQ;

    const int tid = threadIdx.x;
    const int q0  = blockIdx.x * AQ;
    const int h   = blockIdx.y;
    const int b   = blockIdx.z;
    const size_t base = ((size_t)b * SEQ) * HIDDEN + (size_t)h * DK;
    const float scale = 0.08838834764831845f;

    #pragma unroll
    for (int it = 0; it < (AQ * DK) / (256 * 4); it++) {
        int li = (it * 256 + tid) * 4;
        int i = li / DK, d = li % DK;
        float4 v = *(const float4*)(Qg + base + (size_t)(q0 + i) * HIDDEN + d);
        sQ[(d + 0) * AQ + i] = v.x * scale;
        sQ[(d + 1) * AQ + i] = v.y * scale;
        sQ[(d + 2) * AQ + i] = v.z * scale;
        sQ[(d + 3) * AQ + i] = v.w * scale;
    }
    if (tid < AQ) { rmax[tid] = -INFINITY; rsum[tid] = 0.0f; }

    const int tmb = (tid / 16) * 8;
    const int tnb = (tid % 16) * 8;
    float oacc[8][8] = {};

    for (int k0 = 0; k0 < SEQ; k0 += AK) {
        __syncthreads();
        #pragma unroll
        for (int it = 0; it < (AK * DK) / (256 * 4); it++) {
            int li = (it * 256 + tid) * 4;
            int j = li / DK, d = li % DK;
            float4 v = *(const float4*)(Kg + base + (size_t)(k0 + j) * HIDDEN + d);
            sKV[(d + 0) * AK + j] = v.x;
            sKV[(d + 1) * AK + j] = v.y;
            sKV[(d + 2) * AK + j] = v.z;
            sKV[(d + 3) * AK + j] = v.w;
        }
        __syncthreads();

        float sacc[8][8] = {};
        #pragma unroll 8
        for (int d = 0; d < DK; d++) {
            float rm[8], rn[8];
            *(float4*)&rm[0] = *(const float4*)&sQ [d * AQ + tmb];
            *(float4*)&rm[4] = *(const float4*)&sQ [d * AQ + tmb + 4];
            *(float4*)&rn[0] = *(const float4*)&sKV[d * AK + tnb];
            *(float4*)&rn[4] = *(const float4*)&sKV[d * AK + tnb + 4];
            #pragma unroll
            for (int i = 0; i < 8; i++)
                #pragma unroll
                for (int j = 0; j < 8; j++)
                    sacc[i][j] += rm[i] * rn[j];
        }
        #pragma unroll
        for (int j = 0; j < 8; j++) {
            float* sp = sS + (size_t)(tnb + j) * SS_LD + tmb;
            *(float4*)(sp + 0) = make_float4(sacc[0][j], sacc[1][j], sacc[2][j], sacc[3][j]);
            *(float4*)(sp + 4) = make_float4(sacc[4][j], sacc[5][j], sacc[6][j], sacc[7][j]);
        }
        __syncthreads();

        #pragma unroll
        for (int it = 0; it < (AK * DK) / (256 * 4); it++) {
            int li = (it * 256 + tid) * 4;
            int j = li / DK, d = li % DK;
            *(float4*)(sKV + (size_t)j * DK + d) =
                *(const float4*)(Vg + base + (size_t)(k0 + j) * HIDDEN + d);
        }
        if (tid < AQ) {
            const int r = tid;
            float m0 = rmax[r];
            float tmax = m0;
            #pragma unroll 8
            for (int j = 0; j < AK; j++)
                tmax = fmaxf(tmax, sS[(size_t)j * SS_LD + r]);
            float corr = __expf(m0 - tmax);
            float s = 0.0f;
            #pragma unroll 8
            for (int j = 0; j < AK; j++) {
                float e = __expf(sS[(size_t)j * SS_LD + r] - tmax);
                sS[(size_t)j * SS_LD + r] = e;
                s += e;
            }
            rmax[r] = tmax;
            rsum[r] = rsum[r] * corr + s;
            rcor[r] = corr;
        }
        __syncthreads();

        #pragma unroll
        for (int i = 0; i < 8; i++) {
            float cc = rcor[tmb + i];
            #pragma unroll
            for (int j = 0; j < 8; j++) oacc[i][j] *= cc;
        }
        #pragma unroll 4
        for (int j = 0; j < AK; j++) {
            float rp[8], rv[8];
            *(float4*)&rp[0] = *(const float4*)&sS [(size_t)j * SS_LD + tmb];
            *(float4*)&rp[4] = *(const float4*)&sS [(size_t)j * SS_LD + tmb + 4];
            *(float4*)&rv[0] = *(const float4*)&sKV[(size_t)j * DK + tnb];
            *(float4*)&rv[4] = *(const float4*)&sKV[(size_t)j * DK + tnb + 4];
            #pragma unroll
            for (int i = 0; i < 8; i++)
                #pragma unroll
                for (int jj = 0; jj < 8; jj++)
                    oacc[i][jj] += rp[i] * rv[jj];
        }
    }

    #pragma unroll
    for (int i = 0; i < 8; i++) {
        float inv = 1.0f / rsum[tmb + i];
        float* op = Og + base + (size_t)(q0 + tmb + i) * HIDDEN + tnb;
        *(float4*)(op + 0) = make_float4(oacc[i][0] * inv, oacc[i][1] * inv,
                                         oacc[i][2] * inv, oacc[i][3] * inv);
        *(float4*)(op + 4) = make_float4(oacc[i][4] * inv, oacc[i][5] * inv,
                                         oacc[i][6] * inv, oacc[i][7] * inv);
    }
}

// ------------------------------------------------------------------------------
extern "C" void kernel_launch(void* const* d_in, const int* in_sizes, int n_in,
                              void* d_out, int out_size)
{
    const float* x  = (const float*)d_in[0];
    const float* wq = (const float*)d_in[1];
    const float* wk = (const float*)d_in[2];
    const float* wv = (const float*)d_in[3];
    const float* wo = (const float*)d_in[4];
    float* out = (float*)d_out;

    float *qp, *kp, *vp, *aop;
    cudaGetSymbolAddress((void**)&qp,  g_q);
    cudaGetSymbolAddress((void**)&kp,  g_k);
    cudaGetSymbolAddress((void**)&vp,  g_v);
    cudaGetSymbolAddress((void**)&aop, g_ao);

    __nv_bfloat16 *xh, *xl, *wqh, *wql, *wkh, *wkl, *wvh, *wvl, *woh, *wol, *aoh, *aol;
    cudaGetSymbolAddress((void**)&xh,  g_xh);  cudaGetSymbolAddress((void**)&xl,  g_xl);
    cudaGetSymbolAddress((void**)&wqh, g_wqh); cudaGetSymbolAddress((void**)&wql, g_wql);
    cudaGetSymbolAddress((void**)&wkh, g_wkh); cudaGetSymbolAddress((void**)&wkl, g_wkl);
    cudaGetSymbolAddress((void**)&wvh, g_wvh); cudaGetSymbolAddress((void**)&wvl, g_wvl);
    cudaGetSymbolAddress((void**)&woh, g_woh); cudaGetSymbolAddress((void**)&wol, g_wol);
    cudaGetSymbolAddress((void**)&aoh, g_aoh); cudaGetSymbolAddress((void**)&aol, g_aol);

    cudaFuncSetAttribute(gemm_mma_3p, cudaFuncAttributeMaxDynamicSharedMemorySize,
                         SMEM_GEMM);
    size_t smem_attn = (size_t)(DK * AQ + DK * AK + AK * SS_LD + 3 * AQ) * sizeof(float);
    cudaFuncSetAttribute(attn_kernel, cudaFuncAttributeMaxDynamicSharedMemorySize,
                         (int)smem_attn);

    const int CVT_GRID = (HIDDEN * HIDDEN) / 4 / 256;   // 16384
    cvt_hilo<<<CVT_GRID, 256>>>((const float4*)x,  (__nv_bfloat162*)xh,  (__nv_bfloat162*)xl);
    cvt_hilo<<<CVT_GRID, 256>>>((const float4*)wq, (__nv_bfloat162*)wqh, (__nv_bfloat162*)wql);
    cvt_hilo<<<CVT_GRID, 256>>>((const float4*)wk, (__nv_bfloat162*)wkh, (__nv_bfloat162*)wkl);
    cvt_hilo<<<CVT_GRID, 256>>>((const float4*)wv, (__nv_bfloat162*)wvh, (__nv_bfloat162*)wvl);
    cvt_hilo<<<CVT_GRID, 256>>>((const float4*)wo, (__nv_bfloat162*)woh, (__nv_bfloat162*)wol);

    dim3 gg(HIDDEN / NT, MTOK / MT);   // (32, 32)
    gemm_mma_3p<<<gg, 256, SMEM_GEMM>>>(xh, xl, wqh, wql, qp);
    gemm_mma_3p<<<gg, 256, SMEM_GEMM>>>(xh, xl, wkh, wkl, kp);
    gemm_mma_3p<<<gg, 256, SMEM_GEMM>>>(xh, xl, wvh, wvl, vp);

    dim3 ga(SEQ / AQ, NHEADS, BATCH);  // (16, 32, 2)
    attn_kernel<<<ga, 256, smem_attn>>>(qp, kp, vp, aop);

    cvt_hilo<<<CVT_GRID, 256>>>((const float4*)aop, (__nv_bfloat162*)aoh, (__nv_bfloat162*)aol);
    gemm_mma_3p<<<gg, 256, SMEM_GEMM>>>(aoh, aol, woh, wol, out);
}

// round 5
// speedup vs baseline: 3.9248x; 1.6958x over previous
#include <cuda_runtime.h>
#include <cuda_bf16.h>
#include <math.h>
#include <stdint.h>

#define HIDDEN 4096
#define NHEADS 32
#define DK     128
#define BATCH  2
#define SEQ    2048
#define MTOK   (BATCH*SEQ)   // 4096

// GEMM tiling (mma.sync bf16)
#define MT 128
#define NT 128
#define KC 64
#define NCHUNK (HIDDEN / KC)   // 64
#define TILE_BYTES (128 * 128)
#define STAGE_BYTES (4 * TILE_BYTES)
#define SMEM_GEMM (2 * STAGE_BYTES)   // 128KB

// attention smem layout (bytes)
#define A_SQH 0
#define A_SQL 32768
#define A_SKH 65536
#define A_SKL 98304
#define A_SVH 131072
#define A_SVL 163840
#define SMEM_ATTN 196608

#define LOG2E 1.4426950408889634f
#define QSCALE 0.08838834764831845f   // 1/sqrt(128)

// ---------------- scratch ----------------------------------------------------
__device__ __nv_bfloat16 g_qh [MTOK * HIDDEN];
__device__ __nv_bfloat16 g_ql [MTOK * HIDDEN];
__device__ __nv_bfloat16 g_kh [MTOK * HIDDEN];
__device__ __nv_bfloat16 g_kl [MTOK * HIDDEN];
__device__ __nv_bfloat16 g_vh [MTOK * HIDDEN];
__device__ __nv_bfloat16 g_vl [MTOK * HIDDEN];
__device__ __nv_bfloat16 g_aoh[MTOK * HIDDEN];
__device__ __nv_bfloat16 g_aol[MTOK * HIDDEN];
__device__ __nv_bfloat16 g_xh [MTOK * HIDDEN];
__device__ __nv_bfloat16 g_xl [MTOK * HIDDEN];
__device__ __nv_bfloat16 g_wqh[HIDDEN * HIDDEN];
__device__ __nv_bfloat16 g_wql[HIDDEN * HIDDEN];
__device__ __nv_bfloat16 g_wkh[HIDDEN * HIDDEN];
__device__ __nv_bfloat16 g_wkl[HIDDEN * HIDDEN];
__device__ __nv_bfloat16 g_wvh[HIDDEN * HIDDEN];
__device__ __nv_bfloat16 g_wvl[HIDDEN * HIDDEN];
__device__ __nv_bfloat16 g_woh[HIDDEN * HIDDEN];
__device__ __nv_bfloat16 g_wol[HIDDEN * HIDDEN];

// ---------------- PTX helpers -------------------------------------------------
__device__ __forceinline__ uint32_t smem_u32(const void* p) {
    uint32_t a;
    asm("{ .reg .u64 t; cvta.to.shared.u64 t, %1; cvt.u32.u64 %0, t; }"
        : "=r"(a) : "l"(p));
    return a;
}
__device__ __forceinline__ void cp16(uint32_t dst, const void* src) {
    asm volatile("cp.async.cg.shared.global [%0], [%1], 16;"
                 :: "r"(dst), "l"(src) : "memory");
}
#define CP_COMMIT() asm volatile("cp.async.commit_group;" ::: "memory")
#define CP_WAIT(n)  asm volatile("cp.async.wait_group %0;" :: "n"(n) : "memory")

__device__ __forceinline__ void ldsm_x4(uint32_t& r0, uint32_t& r1,
                                        uint32_t& r2, uint32_t& r3, uint32_t a) {
    asm volatile("ldmatrix.sync.aligned.m8n8.x4.shared.b16 {%0,%1,%2,%3}, [%4];"
                 : "=r"(r0), "=r"(r1), "=r"(r2), "=r"(r3) : "r"(a));
}
__device__ __forceinline__ void ldsm_x4_t(uint32_t& r0, uint32_t& r1,
                                          uint32_t& r2, uint32_t& r3, uint32_t a) {
    asm volatile("ldmatrix.sync.aligned.m8n8.x4.trans.shared.b16 {%0,%1,%2,%3}, [%4];"
                 : "=r"(r0), "=r"(r1), "=r"(r2), "=r"(r3) : "r"(a));
}
__device__ __forceinline__ void mma_bf16(float* c, const uint32_t* a,
                                         uint32_t b0, uint32_t b1) {
    asm volatile(
        "mma.sync.aligned.m16n8k16.row.col.f32.bf16.bf16.f32 "
        "{%0,%1,%2,%3}, {%4,%5,%6,%7}, {%8,%9}, {%0,%1,%2,%3};"
        : "+f"(c[0]), "+f"(c[1]), "+f"(c[2]), "+f"(c[3])
        : "r"(a[0]), "r"(a[1]), "r"(a[2]), "r"(a[3]), "r"(b0), "r"(b1));
}
__device__ __forceinline__ uint32_t packbf2(__nv_bfloat16 a, __nv_bfloat16 b) {
    __nv_bfloat162 t = __halves2bfloat162(a, b);
    return *(uint32_t*)&t;
}
__device__ __forceinline__ void split2(float a, float b, uint32_t& hi, uint32_t& lo) {
    __nv_bfloat16 ha = __float2bfloat16(a), hb = __float2bfloat16(b);
    __nv_bfloat16 la = __float2bfloat16(a - __bfloat162float(ha));
    __nv_bfloat16 lb = __float2bfloat16(b - __bfloat162float(hb));
    hi = packbf2(ha, hb);
    lo = packbf2(la, lb);
}

// ---------------- fp32 -> bf16 hi/lo split -------------------------------------
__global__ __launch_bounds__(256) void cvt_hilo(const float4* __restrict__ s,
                                                __nv_bfloat162* __restrict__ h,
                                                __nv_bfloat162* __restrict__ l)
{
    size_t i = (size_t)blockIdx.x * 256 + threadIdx.x;
    float4 v = s[i];
    uint32_t h0, l0, h1, l1;
    split2(v.x, v.y, h0, l0);
    split2(v.z, v.w, h1, l1);
    ((uint32_t*)h)[2*i]   = h0;
    ((uint32_t*)h)[2*i+1] = h1;
    ((uint32_t*)l)[2*i]   = l0;
    ((uint32_t*)l)[2*i+1] = l1;
}

// ---------------- bf16 3-pass GEMM via mma.sync --------------------------------
// C = (Ah+Al)[M,K] @ (Bh+Bl)[N,K]^T (drop Al*Bl).
// If Cf != nullptr: write fp32. Else: write scaled hi/lo bf16 to Ch/Cl.
__global__ __launch_bounds__(256)
void gemm_mma_3p(const __nv_bfloat16* __restrict__ Ah,
                 const __nv_bfloat16* __restrict__ Al,
                 const __nv_bfloat16* __restrict__ Bh,
                 const __nv_bfloat16* __restrict__ Bl,
                 float* __restrict__ Cf,
                 __nv_bfloat16* __restrict__ Ch,
                 __nv_bfloat16* __restrict__ Cl,
                 float scale)
{
    extern __shared__ __align__(1024) char smem[];
    const uint32_t sb = smem_u32(smem);
    const int tid  = threadIdx.x;
    const int wid  = tid >> 5;
    const int lane = tid & 31;
    const int bm   = blockIdx.y * MT;
    const int bn   = blockIdx.x * NT;

    const int wm0 = (wid & 1) * 64;
    const int wn0 = (wid >> 1) * 32;

    const char* gsrc[4] = {
        (const char*)Ah + (size_t)bm * (HIDDEN * 2),
        (const char*)Al + (size_t)bm * (HIDDEN * 2),
        (const char*)Bh + (size_t)bn * (HIDDEN * 2),
        (const char*)Bl + (size_t)bn * (HIDDEN * 2)
    };

    uint32_t ld_sw[4], ld_go[4];
    #pragma unroll
    for (int r = 0; r < 4; r++) {
        int idx = r * 256 + tid;
        uint32_t bo = (uint32_t)idx << 4;
        ld_sw[r] = bo ^ ((bo >> 3) & 0x70);
        ld_go[r] = (uint32_t)(idx >> 3) * (HIDDEN * 2) + (uint32_t)(idx & 7) * 16;
    }

    const int a_r = lane & 15;
    const uint32_t a_k16 = (lane >> 4) * 16;
    uint32_t a_rb[4], a_xm[4];
    #pragma unroll
    for (int i = 0; i < 4; i++) {
        int row = wm0 + i * 16 + a_r;
        a_rb[i] = (uint32_t)row * 128;
        a_xm[i] = (uint32_t)(row & 7) * 16;
    }
    const int b_r = ((lane >> 4) & 1) * 8 + (lane & 7);
    const uint32_t b_k16 = ((lane >> 3) & 1) * 16;
    uint32_t b_rb[2], b_xm[2];
    #pragma unroll
    for (int j = 0; j < 2; j++) {
        int row = wn0 + j * 16 + b_r;
        b_rb[j] = (uint32_t)row * 128;
        b_xm[j] = (uint32_t)(row & 7) * 16;
    }

    float acc[4][4][4] = {};

    auto load_stage = [&](int s, int c) {
        const uint32_t st = sb + (uint32_t)s * STAGE_BYTES;
        #pragma unroll
        for (int t = 0; t < 4; t++) {
            const char* g = gsrc[t] + (size_t)c * 128;
            const uint32_t tb = st + (uint32_t)t * TILE_BYTES;
            #pragma unroll
            for (int r = 0; r < 4; r++)
                cp16(tb + ld_sw[r], g + ld_go[r]);
        }
        CP_COMMIT();
    };

    load_stage(0, 0);

    for (int c = 0; c < NCHUNK; c++) {
        if (c + 1 < NCHUNK) {
            load_stage((c + 1) & 1, c + 1);
            CP_WAIT(1);
        } else {
            CP_WAIT(0);
        }
        __syncthreads();

        const uint32_t st  = sb + (uint32_t)(c & 1) * STAGE_BYTES;
        const uint32_t tAh = st;
        const uint32_t tAl = st + TILE_BYTES;
        const uint32_t tBh = st + 2 * TILE_BYTES;
        const uint32_t tBl = st + 3 * TILE_BYTES;

        #pragma unroll
        for (int ks = 0; ks < 4; ks++) {
            const uint32_t ak = (uint32_t)ks * 32 + a_k16;
            const uint32_t bk = (uint32_t)ks * 32 + b_k16;

            uint32_t ah[4][4], al[4][4], bh[2][4], bl[2][4];
            #pragma unroll
            for (int i = 0; i < 4; i++) {
                uint32_t off = a_rb[i] + (ak ^ a_xm[i]);
                ldsm_x4(ah[i][0], ah[i][1], ah[i][2], ah[i][3], tAh + off);
                ldsm_x4(al[i][0], al[i][1], al[i][2], al[i][3], tAl + off);
            }
            #pragma unroll
            for (int j = 0; j < 2; j++) {
                uint32_t off = b_rb[j] + (bk ^ b_xm[j]);
                ldsm_x4(bh[j][0], bh[j][1], bh[j][2], bh[j][3], tBh + off);
                ldsm_x4(bl[j][0], bl[j][1], bl[j][2], bl[j][3], tBl + off);
            }
            #pragma unroll
            for (int i = 0; i < 4; i++) {
                #pragma unroll
                for (int j = 0; j < 4; j++) {
                    uint32_t B0h = bh[j >> 1][(j & 1) * 2];
                    uint32_t B1h = bh[j >> 1][(j & 1) * 2 + 1];
                    uint32_t B0l = bl[j >> 1][(j & 1) * 2];
                    uint32_t B1l = bl[j >> 1][(j & 1) * 2 + 1];
                    mma_bf16(acc[i][j], ah[i], B0h, B1h);
                    mma_bf16(acc[i][j], ah[i], B0l, B1l);
                    mma_bf16(acc[i][j], al[i], B0h, B1h);
                }
            }
        }
        __syncthreads();
    }

    const int cr = lane >> 2;
    const int cc = (lane & 3) * 2;
    #pragma unroll
    for (int i = 0; i < 4; i++) {
        #pragma unroll
        for (int j = 0; j < 4; j++) {
            int row = bm + wm0 + i * 16 + cr;
            int col = bn + wn0 + j * 8 + cc;
            if (Cf) {
                *(float2*)(Cf + (size_t)row * HIDDEN + col) =
                    make_float2(acc[i][j][0], acc[i][j][1]);
                *(float2*)(Cf + (size_t)(row + 8) * HIDDEN + col) =
                    make_float2(acc[i][j][2], acc[i][j][3]);
            } else {
                uint32_t h0, l0, h1, l1;
                split2(acc[i][j][0] * scale, acc[i][j][1] * scale, h0, l0);
                split2(acc[i][j][2] * scale, acc[i][j][3] * scale, h1, l1);
                *(uint32_t*)(Ch + (size_t)row * HIDDEN + col)       = h0;
                *(uint32_t*)(Cl + (size_t)row * HIDDEN + col)       = l0;
                *(uint32_t*)(Ch + (size_t)(row + 8) * HIDDEN + col) = h1;
                *(uint32_t*)(Cl + (size_t)(row + 8) * HIDDEN + col) = l1;
            }
        }
    }
}

// ---------------- flash attention via mma.sync (split bf16, 3-pass) ------------
// CTA: (q-tile 128, head, batch). 8 warps, each owns 16 q rows.
__global__ __launch_bounds__(256)
void attn_mma(const __nv_bfloat16* __restrict__ Qh, const __nv_bfloat16* __restrict__ Ql,
              const __nv_bfloat16* __restrict__ Kh, const __nv_bfloat16* __restrict__ Kl,
              const __nv_bfloat16* __restrict__ Vh, const __nv_bfloat16* __restrict__ Vl,
              __nv_bfloat16* __restrict__ AOh, __nv_bfloat16* __restrict__ AOl)
{
    extern __shared__ __align__(1024) char smem[];
    const uint32_t sb = smem_u32(smem);
    const int tid  = threadIdx.x;
    const int wid  = tid >> 5;
    const int lane = tid & 31;
    const int q0   = blockIdx.x * 128;
    const int h    = blockIdx.y;
    const int b    = blockIdx.z;

    const size_t hb   = ((size_t)b * SEQ) * HIDDEN + (size_t)h * DK;   // elem offset
    const char* gqh = (const char*)(Qh + hb + (size_t)q0 * HIDDEN);
    const char* gql = (const char*)(Ql + hb + (size_t)q0 * HIDDEN);
    const char* gkh = (const char*)(Kh + hb);
    const char* gkl = (const char*)(Kl + hb);
    const char* gvh = (const char*)(Vh + hb);
    const char* gvl = (const char*)(Vl + hb);

    // tile loader: 128 rows x 256B (2 swizzled 16KB chunks)
    auto load_tile = [&](uint32_t soff, const char* g) {
        #pragma unroll
        for (int r = 0; r < 8; r++) {
            int idx = r * 256 + tid;
            int row = idx >> 4, u = idx & 15;
            uint32_t sa = sb + soff + (uint32_t)(u >> 3) * 16384
                        + (uint32_t)row * 128
                        + (((uint32_t)(u & 7) * 16) ^ ((uint32_t)(row & 7) * 16));
            cp16(sa, g + (size_t)row * (HIDDEN * 2) + (size_t)u * 16);
        }
    };

    // preload Q + K tile 0
    load_tile(A_SQH, gqh);
    load_tile(A_SQL, gql);
    load_tile(A_SKH, gkh);
    load_tile(A_SKL, gkl);
    CP_COMMIT();
    CP_WAIT(0);
    __syncthreads();

    float of[16][4] = {};
    float m0 = -INFINITY, m1 = -INFINITY, l0 = 0.f, l1 = 0.f;

    // precomputed ldmatrix offset pieces
    const uint32_t q_row = (uint32_t)(16 * wid + (lane & 15));
    const uint32_t q_kof = (uint32_t)(lane >> 4) * 16;
    const uint32_t q_xm  = (q_row & 7) * 16;
    const uint32_t q_rb  = q_row * 128;

    const uint32_t k_r   = (uint32_t)(((lane >> 4) & 1) * 8 + (lane & 7));
    const uint32_t k_kof = (uint32_t)((lane >> 3) & 1) * 16;

    const int v_grp  = lane >> 3;
    const uint32_t v_krow = (uint32_t)((v_grp & 1) * 8 + (lane & 7));
    const uint32_t v_ncol = (uint32_t)((v_grp >> 1) * 8);

    for (int t = 0; t < 16; t++) {
        // prefetch V_t (overlaps S compute)
        load_tile(A_SVH, gvh + (size_t)t * 128 * (HIDDEN * 2));
        load_tile(A_SVL, gvl + (size_t)t * 128 * (HIDDEN * 2));
        CP_COMMIT();

        // ---- S = Q K^T (3-pass) ----
        float sf[16][4] = {};
        #pragma unroll
        for (int ks = 0; ks < 8; ks++) {
            uint32_t qa = sb + A_SQH + (uint32_t)(ks >> 2) * 16384 + q_rb
                        + ((((uint32_t)(ks & 3) * 32) + q_kof) ^ q_xm);
            uint32_t qh4[4], ql4[4];
            ldsm_x4(qh4[0], qh4[1], qh4[2], qh4[3], qa);
            ldsm_x4(ql4[0], ql4[1], ql4[2], ql4[3], qa + (A_SQL - A_SQH));
            #pragma unroll
            for (int j16 = 0; j16 < 8; j16++) {
                uint32_t krow = (uint32_t)j16 * 16 + k_r;
                uint32_t ka = sb + A_SKH + (uint32_t)(ks >> 2) * 16384 + krow * 128
                            + ((((uint32_t)(ks & 3) * 32) + k_kof) ^ ((krow & 7) * 16));
                uint32_t kh4[4], kl4[4];
                ldsm_x4(kh4[0], kh4[1], kh4[2], kh4[3], ka);
                ldsm_x4(kl4[0], kl4[1], kl4[2], kl4[3], ka + (A_SKL - A_SKH));
                mma_bf16(sf[2*j16],   qh4, kh4[0], kh4[1]);
                mma_bf16(sf[2*j16],   qh4, kl4[0], kl4[1]);
                mma_bf16(sf[2*j16],   ql4, kh4[0], kh4[1]);
                mma_bf16(sf[2*j16+1], qh4, kh4[2], kh4[3]);
                mma_bf16(sf[2*j16+1], qh4, kl4[2], kl4[3]);
                mma_bf16(sf[2*j16+1], ql4, kh4[2], kh4[3]);
            }
        }

        CP_WAIT(0);       // V_t landed
        __syncthreads();  // all warps done reading K buffer

        // prefetch K_{t+1} (overlaps softmax + PV)
        if (t + 1 < 16) {
            load_tile(A_SKH, gkh + (size_t)(t + 1) * 128 * (HIDDEN * 2));
            load_tile(A_SKL, gkl + (size_t)(t + 1) * 128 * (HIDDEN * 2));
            CP_COMMIT();
        }

        // ---- online softmax (registers) ----
        float tm0 = m0, tm1 = m1;
        #pragma unroll
        for (int f = 0; f < 16; f++) {
            tm0 = fmaxf(tm0, fmaxf(sf[f][0], sf[f][1]));
            tm1 = fmaxf(tm1, fmaxf(sf[f][2], sf[f][3]));
        }
        tm0 = fmaxf(tm0, __shfl_xor_sync(0xffffffff, tm0, 1));
        tm0 = fmaxf(tm0, __shfl_xor_sync(0xffffffff, tm0, 2));
        tm1 = fmaxf(tm1, __shfl_xor_sync(0xffffffff, tm1, 1));
        tm1 = fmaxf(tm1, __shfl_xor_sync(0xffffffff, tm1, 2));
        float cor0 = exp2f((m0 - tm0) * LOG2E);
        float cor1 = exp2f((m1 - tm1) * LOG2E);
        m0 = tm0; m1 = tm1;
        float s0 = 0.f, s1 = 0.f;
        #pragma unroll
        for (int f = 0; f < 16; f++) {
            sf[f][0] = exp2f((sf[f][0] - m0) * LOG2E);
            sf[f][1] = exp2f((sf[f][1] - m0) * LOG2E);
            sf[f][2] = exp2f((sf[f][2] - m1) * LOG2E);
            sf[f][3] = exp2f((sf[f][3] - m1) * LOG2E);
            s0 += sf[f][0] + sf[f][1];
            s1 += sf[f][2] + sf[f][3];
        }
        s0 += __shfl_xor_sync(0xffffffff, s0, 1);
        s0 += __shfl_xor_sync(0xffffffff, s0, 2);
        s1 += __shfl_xor_sync(0xffffffff, s1, 1);
        s1 += __shfl_xor_sync(0xffffffff, s1, 2);
        l0 = l0 * cor0 + s0;
        l1 = l1 * cor1 + s1;
        #pragma unroll
        for (int f = 0; f < 16; f++) {
            of[f][0] *= cor0; of[f][1] *= cor0;
            of[f][2] *= cor1; of[f][3] *= cor1;
        }

        // ---- O += P V (3-pass, P split in regs) ----
        #pragma unroll
        for (int ks = 0; ks < 8; ks++) {
            uint32_t pah[4], pal[4];
            split2(sf[2*ks][0],   sf[2*ks][1],   pah[0], pal[0]);
            split2(sf[2*ks][2],   sf[2*ks][3],   pah[1], pal[1]);
            split2(sf[2*ks+1][0], sf[2*ks+1][1], pah[2], pal[2]);
            split2(sf[2*ks+1][2], sf[2*ks+1][3], pah[3], pal[3]);
            uint32_t vkey = (uint32_t)ks * 16 + v_krow;
            #pragma unroll
            for (int j16 = 0; j16 < 8; j16++) {
                uint32_t ncol = (uint32_t)j16 * 16 + v_ncol;
                uint32_t va = sb + A_SVH + (ncol >> 6) * 16384 + vkey * 128
                            + (((ncol & 63) * 2) ^ ((vkey & 7) * 16));
                uint32_t vh4[4], vl4[4];
                ldsm_x4_t(vh4[0], vh4[1], vh4[2], vh4[3], va);
                ldsm_x4_t(vl4[0], vl4[1], vl4[2], vl4[3], va + (A_SVL - A_SVH));
                mma_bf16(of[2*j16],   pah, vh4[0], vh4[1]);
                mma_bf16(of[2*j16],   pah, vl4[0], vl4[1]);
                mma_bf16(of[2*j16],   pal, vh4[0], vh4[1]);
                mma_bf16(of[2*j16+1], pah, vh4[2], vh4[3]);
                mma_bf16(of[2*j16+1], pah, vl4[2], vl4[3]);
                mma_bf16(of[2*j16+1], pal, vh4[2], vh4[3]);
            }
        }

        CP_WAIT(0);       // K_{t+1} landed
        __syncthreads();  // all warps done reading V buffer
    }

    // ---- epilogue ----
    const float inv0 = 1.f / l0;
    const float inv1 = 1.f / l1;
    const int r0 = q0 + 16 * wid + (lane >> 2);
    const int cc = (lane & 3) * 2;
    #pragma unroll
    for (int f = 0; f < 16; f++) {
        int col = f * 8 + cc;
        uint32_t h0, lo0, h1, lo1;
        split2(of[f][0] * inv0, of[f][1] * inv0, h0, lo0);
        split2(of[f][2] * inv1, of[f][3] * inv1, h1, lo1);
        size_t o0 = hb + (size_t)r0 * HIDDEN + col;
        size_t o1 = hb + (size_t)(r0 + 8) * HIDDEN + col;
        *(uint32_t*)(AOh + o0) = h0;
        *(uint32_t*)(AOl + o0) = lo0;
        *(uint32_t*)(AOh + o1) = h1;
        *(uint32_t*)(AOl + o1) = lo1;
    }
}

// ------------------------------------------------------------------------------
extern "C" void kernel_launch(void* const* d_in, const int* in_sizes, int n_in,
                              void* d_out, int out_size)
{
    const float* x  = (const float*)d_in[0];
    const float* wq = (const float*)d_in[1];
    const float* wk = (const float*)d_in[2];
    const float* wv = (const float*)d_in[3];
    const float* wo = (const float*)d_in[4];
    float* out = (float*)d_out;

    __nv_bfloat16 *qh, *ql, *kh, *kl, *vh, *vl, *aoh, *aol, *xh, *xl;
    __nv_bfloat16 *wqh, *wql, *wkh, *wkl, *wvh, *wvl, *woh, *wol;
    cudaGetSymbolAddress((void**)&qh,  g_qh);  cudaGetSymbolAddress((void**)&ql,  g_ql);
    cudaGetSymbolAddress((void**)&kh,  g_kh);  cudaGetSymbolAddress((void**)&kl,  g_kl);
    cudaGetSymbolAddress((void**)&vh,  g_vh);  cudaGetSymbolAddress((void**)&vl,  g_vl);
    cudaGetSymbolAddress((void**)&aoh, g_aoh); cudaGetSymbolAddress((void**)&aol, g_aol);
    cudaGetSymbolAddress((void**)&xh,  g_xh);  cudaGetSymbolAddress((void**)&xl,  g_xl);
    cudaGetSymbolAddress((void**)&wqh, g_wqh); cudaGetSymbolAddress((void**)&wql, g_wql);
    cudaGetSymbolAddress((void**)&wkh, g_wkh); cudaGetSymbolAddress((void**)&wkl, g_wkl);
    cudaGetSymbolAddress((void**)&wvh, g_wvh); cudaGetSymbolAddress((void**)&wvl, g_wvl);
    cudaGetSymbolAddress((void**)&woh, g_woh); cudaGetSymbolAddress((void**)&wol, g_wol);

    cudaFuncSetAttribute(gemm_mma_3p, cudaFuncAttributeMaxDynamicSharedMemorySize,
                         SMEM_GEMM);
    cudaFuncSetAttribute(attn_mma, cudaFuncAttributeMaxDynamicSharedMemorySize,
                         SMEM_ATTN);

    const int CVT_GRID = (HIDDEN * HIDDEN) / 4 / 256;   // 16384
    cvt_hilo<<<CVT_GRID, 256>>>((const float4*)x,  (__nv_bfloat162*)xh,  (__nv_bfloat162*)xl);
    cvt_hilo<<<CVT_GRID, 256>>>((const float4*)wq, (__nv_bfloat162*)wqh, (__nv_bfloat162*)wql);
    cvt_hilo<<<CVT_GRID, 256>>>((const float4*)wk, (__nv_bfloat162*)wkh, (__nv_bfloat162*)wkl);
    cvt_hilo<<<CVT_GRID, 256>>>((const float4*)wv, (__nv_bfloat162*)wvh, (__nv_bfloat162*)wvl);
    cvt_hilo<<<CVT_GRID, 256>>>((const float4*)wo, (__nv_bfloat162*)woh, (__nv_bfloat162*)wol);

    dim3 gg(HIDDEN / NT, MTOK / MT);   // (32, 32)
    gemm_mma_3p<<<gg, 256, SMEM_GEMM>>>(xh, xl, wqh, wql, nullptr, qh, ql, QSCALE);
    gemm_mma_3p<<<gg, 256, SMEM_GEMM>>>(xh, xl, wkh, wkl, nullptr, kh, kl, 1.0f);
    gemm_mma_3p<<<gg, 256, SMEM_GEMM>>>(xh, xl, wvh, wvl, nullptr, vh, vl, 1.0f);

    dim3 ga(SEQ / 128, NHEADS, BATCH); // (16, 32, 2)
    attn_mma<<<ga, 256, SMEM_ATTN>>>(qh, ql, kh, kl, vh, vl, aoh, aol);

    gemm_mma_3p<<<gg, 256, SMEM_GEMM>>>(aoh, aol, woh, wol, out, nullptr, nullptr, 1.0f);
}